// round 7
// baseline (speedup 1.0000x reference)
#include <cuda_runtime.h>

#define FULL 0xFFFFFFFFu
typedef unsigned long long u64;

constexpr int B = 2048;
constexpr int T = 4096;

__device__ __forceinline__ float tanhf_a(float x){ float y; asm("tanh.approx.f32 %0,%1;":"=f"(y):"f"(x)); return y; }
// sm_103a packed f32x2 ops (ptxas never auto-fuses these from C++)
__device__ __forceinline__ u64 ffma2(u64 a, u64 b, u64 c){
    u64 d; asm("fma.rn.f32x2 %0,%1,%2,%3;" : "=l"(d) : "l"(a), "l"(b), "l"(c)); return d;
}
__device__ __forceinline__ u64 fmul2(u64 a, u64 b){
    u64 d; asm("mul.rn.f32x2 %0,%1,%2;" : "=l"(d) : "l"(a), "l"(b)); return d;
}
__device__ __forceinline__ u64 fadd2(u64 a, u64 b){
    u64 d; asm("add.rn.f32x2 %0,%1,%2;" : "=l"(d) : "l"(a), "l"(b)); return d;
}
__device__ __forceinline__ u64 pack2(float lo, float hi){
    u64 d; asm("mov.b64 %0,{%1,%2};" : "=l"(d) : "f"(lo), "f"(hi)); return d;
}
__device__ __forceinline__ void unpack2(u64 v, float& lo, float& hi){
    asm("mov.b64 {%0,%1},%2;" : "=f"(lo), "=f"(hi) : "l"(v));
}
__device__ __forceinline__ u64 dup2(float v){ return pack2(v, v); }

// 4 batches per warp; lane = (batch b_local = lane>>3, unit u = lane&7).
// Each lane computes all 4 gates (i,f,g,o) of its unit, pair-packed as
// (i,f) and (g,o) in f32x2.
// Per loop body: L1-matvec reads h1[t] FIRST, then L0 produces h1[t+1]
// (in place), then L1's activation/c/head tail runs — two ~indep chains.
// Matvec accumulators split 4+4 deep to halve dependency depth.
// Activations via MUFU.TANH: sigmoid(z) = 0.5*tanh(0.5 z)+0.5, the 0.5
// pre-folded into weights/biases of the sigmoid gates (i,f,o).
__global__ void __launch_bounds__(128, 1)
lstm2_kernel(const float* __restrict__ x,
             const float* __restrict__ Wih0, const float* __restrict__ Whh0,
             const float* __restrict__ bih0, const float* __restrict__ bhh0,
             const float* __restrict__ Wih1, const float* __restrict__ Whh1,
             const float* __restrict__ bih1, const float* __restrict__ bhh1,
             const float* __restrict__ Wlin, const float* __restrict__ blin,
             float* __restrict__ out)
{
    const int lane = threadIdx.x & 31;
    const int warp = (blockIdx.x * blockDim.x + threadIdx.x) >> 5;
    const int u    = lane & 7;
    const int base = lane & 24;                  // first lane of this batch group
    const int b    = warp * 4 + (lane >> 3);     // my batch element

    const float Hs = 0.5f;                       // sigmoid gates: pre-scale 1/2
    const float Gs = 1.0f;                       // tanh gate: direct

    // ---- weights: pre-scaled by activation constant, pair-packed ----
    u64 whh0_if[8], whh0_go[8], wih1_if[8], wih1_go[8], whh1_if[8], whh1_go[8];
#pragma unroll
    for (int k = 0; k < 8; k++) {
        whh0_if[k] = pack2(Hs*Whh0[u*8+k],        Hs*Whh0[(8+u)*8+k]);
        whh0_go[k] = pack2(Gs*Whh0[(16+u)*8+k],   Hs*Whh0[(24+u)*8+k]);
        wih1_if[k] = pack2(Hs*Wih1[u*8+k],        Hs*Wih1[(8+u)*8+k]);
        wih1_go[k] = pack2(Gs*Wih1[(16+u)*8+k],   Hs*Wih1[(24+u)*8+k]);
        whh1_if[k] = pack2(Hs*Whh1[u*8+k],        Hs*Whh1[(8+u)*8+k]);
        whh1_go[k] = pack2(Gs*Whh1[(16+u)*8+k],   Hs*Whh1[(24+u)*8+k]);
    }
    const u64 wx_if0 = pack2(Hs*Wih0[u],      Hs*Wih0[8+u]);
    const u64 wx_go0 = pack2(Gs*Wih0[16+u],   Hs*Wih0[24+u]);
    const u64 b_if0  = pack2(Hs*(bih0[u]+bhh0[u]),       Hs*(bih0[8+u]+bhh0[8+u]));
    const u64 b_go0  = pack2(Gs*(bih0[16+u]+bhh0[16+u]), Hs*(bih0[24+u]+bhh0[24+u]));
    const u64 b_if1  = pack2(Hs*(bih1[u]+bhh1[u]),       Hs*(bih1[8+u]+bhh1[8+u]));
    const u64 b_go1  = pack2(Gs*(bih1[16+u]+bhh1[16+u]), Hs*(bih1[24+u]+bhh1[24+u]));
    float wl[8];
#pragma unroll
    for (int k = 0; k < 8; k++) wl[k] = Wlin[k];
    const float blv = blin[0];

    // ---- state: h vectors kept dup-packed (v,v) for f32x2 matvecs ----
    u64 h1x[8], h2x[8];
#pragma unroll
    for (int k = 0; k < 8; k++) { h1x[k] = 0ull; h2x[k] = 0ull; }
    float c1 = 0.f, c2 = 0.f, pbuf = 0.f;

    const float4* xb4 = reinterpret_cast<const float4*>(x + (size_t)b * T);
    float*        ob  = out + (size_t)b * T;

    // L0: consumes x[t+1] + h1x (= h1[t]), produces h1x = h1[t+1], c1.
    auto L0 = [&](float xt) {
        u64 xd   = dup2(xt);
        u64 aif0 = ffma2(wx_if0, xd, b_if0);     // chain A: x + k0..3 (depth 5)
        u64 ago0 = ffma2(wx_go0, xd, b_go0);
        u64 aif1 = fmul2(whh0_if[4], h1x[4]);    // chain B: k4..7 (depth 4)
        u64 ago1 = fmul2(whh0_go[4], h1x[4]);
#pragma unroll
        for (int k = 0; k < 4; k++) {
            aif0 = ffma2(whh0_if[k], h1x[k], aif0);
            ago0 = ffma2(whh0_go[k], h1x[k], ago0);
        }
#pragma unroll
        for (int k = 5; k < 8; k++) {
            aif1 = ffma2(whh0_if[k], h1x[k], aif1);
            ago1 = ffma2(whh0_go[k], h1x[k], ago1);
        }
        u64 aif = fadd2(aif0, aif1);
        u64 ago = fadd2(ago0, ago1);
        float zi, zf, zg, zo;
        unpack2(aif, zi, zf);
        unpack2(ago, zg, zo);
        float iv = fmaf(0.5f, tanhf_a(zi), 0.5f);
        float fv = fmaf(0.5f, tanhf_a(zf), 0.5f);
        float gv = tanhf_a(zg);
        float ov = fmaf(0.5f, tanhf_a(zo), 0.5f);
        c1 = fmaf(fv, c1, iv * gv);
        float h = ov * tanhf_a(c1);
#pragma unroll
        for (int k = 0; k < 8; k++)
            h1x[k] = dup2(__shfl_sync(FULL, h, base + k));
    };

    // prologue: compute h1[0] from x[0]
    float4 xv = xb4[u];                          // chunk 0: lane holds x[b][4u..4u+3]
    L0(__shfl_sync(FULL, xv.x, base));

    for (int t0 = 0; t0 < T; t0 += 32) {
        float4 xvn = make_float4(0.f, 0.f, 0.f, 0.f);
        if (t0 + 32 < T) xvn = xb4[(t0 + 32) / 4 + u];   // prefetch next chunk

#pragma unroll 1
        for (int sub = 0; sub < 8; sub++) {
#pragma unroll
            for (int q = 0; q < 4; q++) {
                // ==== L1 matvec for step t = t0+4*sub+q : reads h1x=h1[t] ====
                // 4 accumulators, 4-deep chains
                u64 aif0 = b_if1, ago0 = b_go1;
                u64 aif1 = fmul2(wih1_if[4], h1x[4]);
                u64 ago1 = fmul2(wih1_go[4], h1x[4]);
                u64 bif0 = fmul2(whh1_if[0], h2x[0]);
                u64 bgo0 = fmul2(whh1_go[0], h2x[0]);
                u64 bif1 = fmul2(whh1_if[4], h2x[4]);
                u64 bgo1 = fmul2(whh1_go[4], h2x[4]);
#pragma unroll
                for (int k = 0; k < 4; k++) {
                    aif0 = ffma2(wih1_if[k], h1x[k], aif0);
                    ago0 = ffma2(wih1_go[k], h1x[k], ago0);
                }
#pragma unroll
                for (int k = 5; k < 8; k++) {
                    aif1 = ffma2(wih1_if[k], h1x[k], aif1);
                    ago1 = ffma2(wih1_go[k], h1x[k], ago1);
                }
#pragma unroll
                for (int k = 1; k < 4; k++) {
                    bif0 = ffma2(whh1_if[k], h2x[k], bif0);
                    bgo0 = ffma2(whh1_go[k], h2x[k], bgo0);
                }
#pragma unroll
                for (int k = 5; k < 8; k++) {
                    bif1 = ffma2(whh1_if[k], h2x[k], bif1);
                    bgo1 = ffma2(whh1_go[k], h2x[k], bgo1);
                }

                // ==== L0 for x-step t+1 (independent chain, h1x -> h1[t+1]) ====
                {
                    float xsrc; int srcl;
                    if      (q == 0) { xsrc = xv.y; srcl = base + sub; }
                    else if (q == 1) { xsrc = xv.z; srcl = base + sub; }
                    else if (q == 2) { xsrc = xv.w; srcl = base + sub; }
                    else             { xsrc = (sub == 7) ? xvn.x : xv.x;
                                       srcl = base + ((sub + 1) & 7); }
                    L0(__shfl_sync(FULL, xsrc, srcl));
                    // last step computes a harmless garbage h1[T] from the
                    // zero-filled xvn (never read, no OOB access)
                }

                // ==== L1 tail: activations, c2, h2, head ====
                u64 aif = fadd2(fadd2(aif0, aif1), fadd2(bif0, bif1));
                u64 ago = fadd2(fadd2(ago0, ago1), fadd2(bgo0, bgo1));
                float zi, zf, zg, zo;
                unpack2(aif, zi, zf);
                unpack2(ago, zg, zo);
                float iv = fmaf(0.5f, tanhf_a(zi), 0.5f);
                float fv = fmaf(0.5f, tanhf_a(zf), 0.5f);
                float gv = tanhf_a(zg);
                float ov = fmaf(0.5f, tanhf_a(zo), 0.5f);
                c2 = fmaf(fv, c2, iv * gv);
                float h2 = ov * tanhf_a(c2);
                // distribute h2, compute head on the fly
                float p = blv;
#pragma unroll
                for (int k = 0; k < 8; k++) {
                    float hs = __shfl_sync(FULL, h2, base + k);
                    p = fmaf(wl[k], hs, p);
                    h2x[k] = dup2(hs);
                }
                if (((sub * 4 + q) & 7) == u) pbuf = p;   // bank out[t] in lane t&7
            }
            if (sub & 1)                          // 8 steps banked -> coalesced store
                ob[t0 + sub * 4 - 4 + u] = pbuf;
        }
        xv = xvn;
    }
}

extern "C" void kernel_launch(void* const* d_in, const int* in_sizes, int n_in,
                              void* d_out, int out_size)
{
    const float* x    = (const float*)d_in[0];
    const float* Wih0 = (const float*)d_in[1];
    const float* Whh0 = (const float*)d_in[2];
    const float* bih0 = (const float*)d_in[3];
    const float* bhh0 = (const float*)d_in[4];
    const float* Wih1 = (const float*)d_in[5];
    const float* Whh1 = (const float*)d_in[6];
    const float* bih1 = (const float*)d_in[7];
    const float* bhh1 = (const float*)d_in[8];
    const float* Wlin = (const float*)d_in[9];
    const float* blin = (const float*)d_in[10];
    float* out = (float*)d_out;

    // 512 warps (4 batches each); 128-thread blocks so the block's 4 warps
    // land on all 4 SMSPs (wid%4) -> 128 blocks.
    const int threads = 128;
    const int blocks  = (B / 4) * 32 / threads;   // 128
    lstm2_kernel<<<blocks, threads>>>(x, Wih0, Whh0, bih0, bhh0,
                                      Wih1, Whh1, bih1, bhh1, Wlin, blin, out);
}

// round 8
// speedup vs baseline: 1.0246x; 1.0246x over previous
#include <cuda_runtime.h>

#define FULL 0xFFFFFFFFu
typedef unsigned long long u64;

constexpr int B = 2048;
constexpr int T = 4096;
constexpr int CH = 8;              // steps per chunk
constexpr int NCHUNK = T / CH;     // 512

__device__ __forceinline__ float tanhf_a(float x){ float y; asm("tanh.approx.f32 %0,%1;":"=f"(y):"f"(x)); return y; }
__device__ __forceinline__ u64 ffma2(u64 a, u64 b, u64 c){
    u64 d; asm("fma.rn.f32x2 %0,%1,%2,%3;" : "=l"(d) : "l"(a), "l"(b), "l"(c)); return d;
}
__device__ __forceinline__ u64 fmul2(u64 a, u64 b){
    u64 d; asm("mul.rn.f32x2 %0,%1,%2;" : "=l"(d) : "l"(a), "l"(b)); return d;
}
__device__ __forceinline__ u64 fadd2(u64 a, u64 b){
    u64 d; asm("add.rn.f32x2 %0,%1,%2;" : "=l"(d) : "l"(a), "l"(b)); return d;
}
__device__ __forceinline__ u64 pack2(float lo, float hi){
    u64 d; asm("mov.b64 %0,{%1,%2};" : "=l"(d) : "f"(lo), "f"(hi)); return d;
}
__device__ __forceinline__ void unpack2(u64 v, float& lo, float& hi){
    asm("mov.b64 {%0,%1},%2;" : "=f"(lo), "=f"(hi) : "l"(v));
}
__device__ __forceinline__ u64 dup2(float v){ return pack2(v, v); }
__device__ __forceinline__ void pbar(int id){ asm volatile("bar.sync %0, 64;" :: "r"(id) : "memory"); }

// Producer/consumer layer split. 256-thread blocks = 4 warp pairs.
// Pair k: A = wid k (SMSP k), B = wid k+4 (same SMSP k) -> 2 warps/SMSP.
// Each pair owns 4 batches; lane = (b_local = lane>>3, unit u = lane&7),
// each lane computes all 4 gates of its unit, pair-packed (i,f),(g,o) f32x2.
// A: layer-0 recurrence + L1 input matvec (b1 + Wih1*h1[t]) -> smem ring.
// B: layer-1 recurrence (Whh1*h2 only) + activations + head + store.
// Double-buffered 8-step chunks, one named barrier per chunk; B lags 1 chunk.
// Activations via MUFU.TANH: sigmoid(z)=0.5*tanh(0.5z)+0.5, 0.5 pre-folded.
__global__ void __launch_bounds__(256, 1)
lstm2_kernel(const float* __restrict__ x,
             const float* __restrict__ Wih0, const float* __restrict__ Whh0,
             const float* __restrict__ bih0, const float* __restrict__ bhh0,
             const float* __restrict__ Wih1, const float* __restrict__ Whh1,
             const float* __restrict__ bih1, const float* __restrict__ bhh1,
             const float* __restrict__ Wlin, const float* __restrict__ blin,
             float* __restrict__ out)
{
    __shared__ __align__(16) u64 ring[4][2][CH][32][2];  // 32 KB
    __shared__ __align__(16) u64 hdup[4][2][32];         // 2 KB (B h2 redist)

    const int tid  = threadIdx.x;
    const int lane = tid & 31;
    const int wid  = tid >> 5;
    const bool isA = (wid < 4);
    const int pair = wid & 3;
    const int u    = lane & 7;
    const int base = lane & 24;
    const int bb   = blockIdx.x * 16 + pair * 4;    // first batch of this pair
    const int barid = 1 + pair;

    const float Hs = 0.5f;

    if (isA) {
        // ================= producer: layer 0 + L1-input matvec =================
        u64 whh0_if[8], whh0_go[8], wih1_if[8], wih1_go[8];
#pragma unroll
        for (int k = 0; k < 8; k++) {
            whh0_if[k] = pack2(Hs*Whh0[u*8+k],      Hs*Whh0[(8+u)*8+k]);
            whh0_go[k] = pack2(Whh0[(16+u)*8+k],    Hs*Whh0[(24+u)*8+k]);
            wih1_if[k] = pack2(Hs*Wih1[u*8+k],      Hs*Wih1[(8+u)*8+k]);
            wih1_go[k] = pack2(Wih1[(16+u)*8+k],    Hs*Wih1[(24+u)*8+k]);
        }
        const u64 wx_if0 = pack2(Hs*Wih0[u],    Hs*Wih0[8+u]);
        const u64 wx_go0 = pack2(Wih0[16+u],    Hs*Wih0[24+u]);
        const u64 b_if0  = pack2(Hs*(bih0[u]+bhh0[u]),      Hs*(bih0[8+u]+bhh0[8+u]));
        const u64 b_go0  = pack2((bih0[16+u]+bhh0[16+u]),   Hs*(bih0[24+u]+bhh0[24+u]));
        const u64 b_if1  = pack2(Hs*(bih1[u]+bhh1[u]),      Hs*(bih1[8+u]+bhh1[8+u]));
        const u64 b_go1  = pack2((bih1[16+u]+bhh1[16+u]),   Hs*(bih1[24+u]+bhh1[24+u]));

        u64 h1x[8];
#pragma unroll
        for (int k = 0; k < 8; k++) h1x[k] = 0ull;
        float c1 = 0.f;

        // lane l holds x[bb + (l>>3)][c*CH + (l&7)]
        const float* xrow = x + (size_t)(bb + (lane >> 3)) * T + (lane & 7);
        float xcur = xrow[0];

        for (int c = 0; c < NCHUNK; c++) {
            float xnext = 0.f;
            if (c + 1 < NCHUNK) xnext = xrow[(c + 1) * CH];

#pragma unroll
            for (int s = 0; s < CH; s++) {
                const float xt = __shfl_sync(FULL, xcur, base + s);
                // ---- L0 matvec (split 4+4 chains) ----
                u64 xd   = dup2(xt);
                u64 aif0 = ffma2(wx_if0, xd, b_if0);
                u64 ago0 = ffma2(wx_go0, xd, b_go0);
                u64 aif1 = fmul2(whh0_if[4], h1x[4]);
                u64 ago1 = fmul2(whh0_go[4], h1x[4]);
#pragma unroll
                for (int k = 0; k < 4; k++) {
                    aif0 = ffma2(whh0_if[k], h1x[k], aif0);
                    ago0 = ffma2(whh0_go[k], h1x[k], ago0);
                }
#pragma unroll
                for (int k = 5; k < 8; k++) {
                    aif1 = ffma2(whh0_if[k], h1x[k], aif1);
                    ago1 = ffma2(whh0_go[k], h1x[k], ago1);
                }
                u64 aif = fadd2(aif0, aif1);
                u64 ago = fadd2(ago0, ago1);
                float zi, zf, zg, zo;
                unpack2(aif, zi, zf);
                unpack2(ago, zg, zo);
                float iv = fmaf(0.5f, tanhf_a(zi), 0.5f);
                float fv = fmaf(0.5f, tanhf_a(zf), 0.5f);
                float gv = tanhf_a(zg);
                float ov = fmaf(0.5f, tanhf_a(zo), 0.5f);
                c1 = fmaf(fv, c1, iv * gv);
                float h = ov * tanhf_a(c1);
                // ---- redistribute h1 (chain-critical: shfl) ----
#pragma unroll
                for (int k = 0; k < 8; k++)
                    h1x[k] = dup2(__shfl_sync(FULL, h, base + k));
                // ---- L1 input matvec (off-chain, single 8-deep chain) ----
                u64 rif = ffma2(wih1_if[0], h1x[0], b_if1);
                u64 rgo = ffma2(wih1_go[0], h1x[0], b_go1);
#pragma unroll
                for (int k = 1; k < 8; k++) {
                    rif = ffma2(wih1_if[k], h1x[k], rif);
                    rgo = ffma2(wih1_go[k], h1x[k], rgo);
                }
                *(ulonglong2*)&ring[pair][c & 1][s][lane][0] = make_ulonglong2(rif, rgo);
            }
            xcur = xnext;
            pbar(barid);
        }
        pbar(barid);                     // cover B's final chunk
    } else {
        // ================= consumer: layer 1 + head =================
        u64 whh1_if[8], whh1_go[8];
#pragma unroll
        for (int k = 0; k < 8; k++) {
            whh1_if[k] = pack2(Hs*Whh1[u*8+k],      Hs*Whh1[(8+u)*8+k]);
            whh1_go[k] = pack2(Whh1[(16+u)*8+k],    Hs*Whh1[(24+u)*8+k]);
        }
        const float wlu = Wlin[u];
        const float blv = blin[0];

        u64 h2x[8];
#pragma unroll
        for (int k = 0; k < 8; k++) h2x[k] = 0ull;
        float c2 = 0.f, pbuf = 0.f;

        float* ob = out + (size_t)(bb + (lane >> 3)) * T;

        pbar(barid);                     // wait for chunk 0
        for (int c = 0; c < NCHUNK; c++) {
#pragma unroll
            for (int s = 0; s < CH; s++) {
                // ring value = b1 + Wih1*h1[t] (ready since previous chunk)
                const ulonglong2 rv = *(const ulonglong2*)&ring[pair][c & 1][s][lane][0];
                // ---- Whh1*h2 matvec (split 4+4 chains) ----
                u64 bif0 = fmul2(whh1_if[0], h2x[0]);
                u64 bgo0 = fmul2(whh1_go[0], h2x[0]);
                u64 bif1 = fmul2(whh1_if[4], h2x[4]);
                u64 bgo1 = fmul2(whh1_go[4], h2x[4]);
#pragma unroll
                for (int k = 1; k < 4; k++) {
                    bif0 = ffma2(whh1_if[k], h2x[k], bif0);
                    bgo0 = ffma2(whh1_go[k], h2x[k], bgo0);
                }
#pragma unroll
                for (int k = 5; k < 8; k++) {
                    bif1 = ffma2(whh1_if[k], h2x[k], bif1);
                    bgo1 = ffma2(whh1_go[k], h2x[k], bgo1);
                }
                u64 aif = fadd2(rv.x, fadd2(bif0, bif1));
                u64 ago = fadd2(rv.y, fadd2(bgo0, bgo1));
                float zi, zf, zg, zo;
                unpack2(aif, zi, zf);
                unpack2(ago, zg, zo);
                float iv = fmaf(0.5f, tanhf_a(zi), 0.5f);
                float fv = fmaf(0.5f, tanhf_a(zf), 0.5f);
                float gv = tanhf_a(zg);
                float ov = fmaf(0.5f, tanhf_a(zo), 0.5f);
                c2 = fmaf(fv, c2, iv * gv);
                float h2 = ov * tanhf_a(c2);
                // ---- head: butterfly reduce within the 8-lane batch group ----
                float p = wlu * h2;
                p += __shfl_xor_sync(FULL, p, 1);
                p += __shfl_xor_sync(FULL, p, 2);
                p += __shfl_xor_sync(FULL, p, 4);
                if (u == s) pbuf = p + blv;          // bank step t in lane t&7
                // ---- redistribute h2: dup-STS.64 + 4x LDS.128 (double-buffered) ----
                hdup[pair][s & 1][lane] = dup2(h2);
                __syncwarp();
#pragma unroll
                for (int j = 0; j < 4; j++) {
                    ulonglong2 v = *(const ulonglong2*)&hdup[pair][s & 1][base + 2 * j];
                    h2x[2 * j]     = v.x;
                    h2x[2 * j + 1] = v.y;
                }
            }
            ob[c * CH + u] = pbuf;                    // 8 banked steps -> coalesced
            pbar(barid);
        }
    }
}

extern "C" void kernel_launch(void* const* d_in, const int* in_sizes, int n_in,
                              void* d_out, int out_size)
{
    const float* x    = (const float*)d_in[0];
    const float* Wih0 = (const float*)d_in[1];
    const float* Whh0 = (const float*)d_in[2];
    const float* bih0 = (const float*)d_in[3];
    const float* bhh0 = (const float*)d_in[4];
    const float* Wih1 = (const float*)d_in[5];
    const float* Whh1 = (const float*)d_in[6];
    const float* bih1 = (const float*)d_in[7];
    const float* bhh1 = (const float*)d_in[8];
    const float* Wlin = (const float*)d_in[9];
    const float* blin = (const float*)d_in[10];
    float* out = (float*)d_out;

    // 16 batches per block (4 pairs x 4 batches); 256 threads; 128 blocks.
    const int threads = 256;
    const int blocks  = B / 16;                   // 128
    lstm2_kernel<<<blocks, threads>>>(x, Wih0, Whh0, bih0, bhh0,
                                      Wih1, Whh1, bih1, bhh1, Wlin, blin, out);
}

// round 10
// speedup vs baseline: 1.0515x; 1.0263x over previous
#include <cuda_runtime.h>

#define FULL 0xFFFFFFFFu
typedef unsigned long long u64;

constexpr int B = 2048;
constexpr int T = 4096;
constexpr int CH = 8;              // steps per chunk
constexpr int NCHUNK = T / CH;     // 512

__device__ __forceinline__ float tanhf_a(float x){ float y; asm("tanh.approx.f32 %0,%1;":"=f"(y):"f"(x)); return y; }
__device__ __forceinline__ u64 ffma2(u64 a, u64 b, u64 c){
    u64 d; asm("fma.rn.f32x2 %0,%1,%2,%3;" : "=l"(d) : "l"(a), "l"(b), "l"(c)); return d;
}
__device__ __forceinline__ u64 fmul2(u64 a, u64 b){
    u64 d; asm("mul.rn.f32x2 %0,%1,%2;" : "=l"(d) : "l"(a), "l"(b)); return d;
}
__device__ __forceinline__ u64 fadd2(u64 a, u64 b){
    u64 d; asm("add.rn.f32x2 %0,%1,%2;" : "=l"(d) : "l"(a), "l"(b)); return d;
}
__device__ __forceinline__ u64 pack2(float lo, float hi){
    u64 d; asm("mov.b64 %0,{%1,%2};" : "=l"(d) : "f"(lo), "f"(hi)); return d;
}
__device__ __forceinline__ void unpack2(u64 v, float& lo, float& hi){
    asm("mov.b64 {%0,%1},%2;" : "=f"(lo), "=f"(hi) : "l"(v));
}
__device__ __forceinline__ u64 dup2(float v){ return pack2(v, v); }
__device__ __forceinline__ void pbar(int id){ asm volatile("bar.sync %0, 64;" :: "r"(id) : "memory"); }

// Producer/consumer layer split. 256-thread blocks = 4 warp pairs.
// Pair k: A = wid k (SMSP k), B = wid k+4 (same SMSP k) -> 2 warps/SMSP.
// Each pair owns 4 batches; lane = (b_local = lane>>3, unit u = lane&7),
// each lane computes all 4 gates of its unit, pair-packed (i,f),(g,o) f32x2.
// A: layer-0 recurrence + L1 input matvec (b1 + Wih1*h1[t]) -> smem ring.
// B: layer-1 recurrence (Whh1*h2) + activations + head + store.
//   B preloads the whole 8-step ring chunk into registers at chunk start
//   (no per-step LDS on the chain) and redistributes h2 via shfl (no
//   STS/WARPSYNC/LDS on the chain).
// Double-buffered 8-step chunks, one named barrier per chunk; B lags 1 chunk.
// Activations via MUFU.TANH: sigmoid(z)=0.5*tanh(0.5z)+0.5, 0.5 pre-folded.
__global__ void __launch_bounds__(256, 1)
lstm2_kernel(const float* __restrict__ x,
             const float* __restrict__ Wih0, const float* __restrict__ Whh0,
             const float* __restrict__ bih0, const float* __restrict__ bhh0,
             const float* __restrict__ Wih1, const float* __restrict__ Whh1,
             const float* __restrict__ bih1, const float* __restrict__ bhh1,
             const float* __restrict__ Wlin, const float* __restrict__ blin,
             float* __restrict__ out)
{
    __shared__ __align__(16) u64 ring[4][2][CH][32][2];  // 32 KB

    const int tid  = threadIdx.x;
    const int lane = tid & 31;
    const int wid  = tid >> 5;
    const bool isA = (wid < 4);
    const int pair = wid & 3;
    const int u    = lane & 7;
    const int base = lane & 24;
    const int bb   = blockIdx.x * 16 + pair * 4;    // first batch of this pair
    const int barid = 1 + pair;

    const float Hs = 0.5f;

    if (isA) {
        // ================= producer: layer 0 + L1-input matvec =================
        u64 whh0_if[8], whh0_go[8], wih1_if[8], wih1_go[8];
#pragma unroll
        for (int k = 0; k < 8; k++) {
            whh0_if[k] = pack2(Hs*Whh0[u*8+k],      Hs*Whh0[(8+u)*8+k]);
            whh0_go[k] = pack2(Whh0[(16+u)*8+k],    Hs*Whh0[(24+u)*8+k]);
            wih1_if[k] = pack2(Hs*Wih1[u*8+k],      Hs*Wih1[(8+u)*8+k]);
            wih1_go[k] = pack2(Wih1[(16+u)*8+k],    Hs*Wih1[(24+u)*8+k]);
        }
        const u64 wx_if0 = pack2(Hs*Wih0[u],    Hs*Wih0[8+u]);
        const u64 wx_go0 = pack2(Wih0[16+u],    Hs*Wih0[24+u]);
        const u64 b_if0  = pack2(Hs*(bih0[u]+bhh0[u]),      Hs*(bih0[8+u]+bhh0[8+u]));
        const u64 b_go0  = pack2((bih0[16+u]+bhh0[16+u]),   Hs*(bih0[24+u]+bhh0[24+u]));
        const u64 b_if1  = pack2(Hs*(bih1[u]+bhh1[u]),      Hs*(bih1[8+u]+bhh1[8+u]));
        const u64 b_go1  = pack2((bih1[16+u]+bhh1[16+u]),   Hs*(bih1[24+u]+bhh1[24+u]));

        u64 h1x[8];
#pragma unroll
        for (int k = 0; k < 8; k++) h1x[k] = 0ull;
        float c1 = 0.f;

        // lane l holds x[bb + (l>>3)][c*CH + (l&7)]
        const float* xrow = x + (size_t)(bb + (lane >> 3)) * T + (lane & 7);
        float xcur = xrow[0];

        for (int c = 0; c < NCHUNK; c++) {
            float xnext = 0.f;
            if (c + 1 < NCHUNK) xnext = xrow[(c + 1) * CH];

#pragma unroll
            for (int s = 0; s < CH; s++) {
                const float xt = __shfl_sync(FULL, xcur, base + s);
                // ---- L0 matvec (split 4+4 chains) ----
                u64 xd   = dup2(xt);
                u64 aif0 = ffma2(wx_if0, xd, b_if0);
                u64 ago0 = ffma2(wx_go0, xd, b_go0);
                u64 aif1 = fmul2(whh0_if[4], h1x[4]);
                u64 ago1 = fmul2(whh0_go[4], h1x[4]);
#pragma unroll
                for (int k = 0; k < 4; k++) {
                    aif0 = ffma2(whh0_if[k], h1x[k], aif0);
                    ago0 = ffma2(whh0_go[k], h1x[k], ago0);
                }
#pragma unroll
                for (int k = 5; k < 8; k++) {
                    aif1 = ffma2(whh0_if[k], h1x[k], aif1);
                    ago1 = ffma2(whh0_go[k], h1x[k], ago1);
                }
                u64 aif = fadd2(aif0, aif1);
                u64 ago = fadd2(ago0, ago1);
                float zi, zf, zg, zo;
                unpack2(aif, zi, zf);
                unpack2(ago, zg, zo);
                float iv = fmaf(0.5f, tanhf_a(zi), 0.5f);
                float fv = fmaf(0.5f, tanhf_a(zf), 0.5f);
                float gv = tanhf_a(zg);
                float ov = fmaf(0.5f, tanhf_a(zo), 0.5f);
                c1 = fmaf(fv, c1, iv * gv);
                float h = ov * tanhf_a(c1);
                // ---- redistribute h1 (chain-critical: shfl) ----
#pragma unroll
                for (int k = 0; k < 8; k++)
                    h1x[k] = dup2(__shfl_sync(FULL, h, base + k));
                // ---- L1 input matvec (off-chain, single 8-deep chain) ----
                u64 rif = ffma2(wih1_if[0], h1x[0], b_if1);
                u64 rgo = ffma2(wih1_go[0], h1x[0], b_go1);
#pragma unroll
                for (int k = 1; k < 8; k++) {
                    rif = ffma2(wih1_if[k], h1x[k], rif);
                    rgo = ffma2(wih1_go[k], h1x[k], rgo);
                }
                *(ulonglong2*)&ring[pair][c & 1][s][lane][0] = make_ulonglong2(rif, rgo);
            }
            xcur = xnext;
            pbar(barid);
        }
        pbar(barid);                     // cover B's final chunk
    } else {
        // ================= consumer: layer 1 + head =================
        u64 whh1_if[8], whh1_go[8];
#pragma unroll
        for (int k = 0; k < 8; k++) {
            whh1_if[k] = pack2(Hs*Whh1[u*8+k],      Hs*Whh1[(8+u)*8+k]);
            whh1_go[k] = pack2(Whh1[(16+u)*8+k],    Hs*Whh1[(24+u)*8+k]);
        }
        const float wlu = Wlin[u];
        const float blv = blin[0];

        u64 h2x[8];
#pragma unroll
        for (int k = 0; k < 8; k++) h2x[k] = 0ull;
        float c2 = 0.f, pbuf = 0.f;

        float* ob = out + (size_t)(bb + (lane >> 3)) * T;

        pbar(barid);                     // wait for chunk 0
        for (int c = 0; c < NCHUNK; c++) {
            // preload the whole chunk of ring values into registers
            // (8x LDS.128, MLP-overlapped; removes LDS from the step chain)
            u64 rif[CH], rgo[CH];
#pragma unroll
            for (int s = 0; s < CH; s++) {
                const ulonglong2 rv = *(const ulonglong2*)&ring[pair][c & 1][s][lane][0];
                rif[s] = rv.x;
                rgo[s] = rv.y;
            }
#pragma unroll
            for (int s = 0; s < CH; s++) {
                // ---- Whh1*h2 matvec, seeded by rif/rgo (split 4+4 chains) ----
                u64 bif0 = ffma2(whh1_if[0], h2x[0], rif[s]);
                u64 bgo0 = ffma2(whh1_go[0], h2x[0], rgo[s]);
                u64 bif1 = fmul2(whh1_if[4], h2x[4]);
                u64 bgo1 = fmul2(whh1_go[4], h2x[4]);
#pragma unroll
                for (int k = 1; k < 4; k++) {
                    bif0 = ffma2(whh1_if[k], h2x[k], bif0);
                    bgo0 = ffma2(whh1_go[k], h2x[k], bgo0);
                }
#pragma unroll
                for (int k = 5; k < 8; k++) {
                    bif1 = ffma2(whh1_if[k], h2x[k], bif1);
                    bgo1 = ffma2(whh1_go[k], h2x[k], bgo1);
                }
                u64 aif = fadd2(bif0, bif1);
                u64 ago = fadd2(bgo0, bgo1);
                float zi, zf, zg, zo;
                unpack2(aif, zi, zf);
                unpack2(ago, zg, zo);
                float iv = fmaf(0.5f, tanhf_a(zi), 0.5f);
                float fv = fmaf(0.5f, tanhf_a(zf), 0.5f);
                float gv = tanhf_a(zg);
                float ov = fmaf(0.5f, tanhf_a(zo), 0.5f);
                c2 = fmaf(fv, c2, iv * gv);
                float h2 = ov * tanhf_a(c2);
                // ---- head: butterfly reduce within the 8-lane batch group ----
                float p = wlu * h2;
                p += __shfl_xor_sync(FULL, p, 1);
                p += __shfl_xor_sync(FULL, p, 2);
                p += __shfl_xor_sync(FULL, p, 4);
                if (u == s) pbuf = p + blv;          // bank step t in lane t&7
                // ---- redistribute h2 via shfl (no smem/syncwarp on chain) ----
#pragma unroll
                for (int k = 0; k < 8; k++)
                    h2x[k] = dup2(__shfl_sync(FULL, h2, base + k));
            }
            ob[c * CH + u] = pbuf;                    // 8 banked steps -> coalesced
            pbar(barid);
        }
    }
}

extern "C" void kernel_launch(void* const* d_in, const int* in_sizes, int n_in,
                              void* d_out, int out_size)
{
    const float* x    = (const float*)d_in[0];
    const float* Wih0 = (const float*)d_in[1];
    const float* Whh0 = (const float*)d_in[2];
    const float* bih0 = (const float*)d_in[3];
    const float* bhh0 = (const float*)d_in[4];
    const float* Wih1 = (const float*)d_in[5];
    const float* Whh1 = (const float*)d_in[6];
    const float* bih1 = (const float*)d_in[7];
    const float* bhh1 = (const float*)d_in[8];
    const float* Wlin = (const float*)d_in[9];
    const float* blin = (const float*)d_in[10];
    float* out = (float*)d_out;

    // 16 batches per block (4 pairs x 4 batches); 256 threads; 128 blocks.
    const int threads = 256;
    const int blocks  = B / 16;                   // 128
    lstm2_kernel<<<blocks, threads>>>(x, Wih0, Whh0, bih0, bhh0,
                                      Wih1, Whh1, bih1, bhh1, Wlin, blin, out);
}